// round 2
// baseline (speedup 1.0000x reference)
#include <cuda_runtime.h>
#include <math.h>

// DenseRNN: B=256, T=1024, D=128, H=128, fp32.
// out[b,h] = final Elman state after 1024 steps.
//
// Layout: 128 CTAs x 256 threads. CTA handles batch rows (2*blockIdx, 2*blockIdx+1).
// Thread = (col = warp*16 + lane%16, half = lane/16). Each thread keeps the
// 64-element k-slice of BOTH weight columns (input w and recurrent W) in
// registers as packed f32x2 pairs and uses fma.rn.f32x2 (Blackwell packed FMA).
// Partial dot products are combined with shfl_xor(16).

#define B_ 256
#define T_ 1024
#define D_ 128
#define H_ 128

typedef unsigned long long u64;

struct alignas(16) u64x2 { u64 a, b; };

__device__ __forceinline__ u64 pk2(float lo, float hi) {
    u64 r; asm("mov.b64 %0, {%1, %2};" : "=l"(r) : "f"(lo), "f"(hi)); return r;
}
__device__ __forceinline__ void upk2(u64 v, float& lo, float& hi) {
    asm("mov.b64 {%0, %1}, %2;" : "=f"(lo), "=f"(hi) : "l"(v));
}
__device__ __forceinline__ u64 ffma2(u64 a, u64 b, u64 c) {
    u64 d; asm("fma.rn.f32x2 %0, %1, %2, %3;" : "=l"(d) : "l"(a), "l"(b), "l"(c));
    return d;
}

__global__ __launch_bounds__(256, 1)
void rnn_fused(const float* __restrict__ x,      // [B,T,D]
               const float* __restrict__ w,      // [D,H]
               const float* __restrict__ Wr,     // [H,H]
               const float* __restrict__ bias,   // [H]
               float* __restrict__ out)          // [B,H]
{
    __shared__ float s_x[2][128];        // [row][d] current timestep input
    __shared__ float s_state[2][2][128]; // [buf][row][col]

    const int tid   = threadIdx.x;
    const int lane  = tid & 31;
    const int warp  = tid >> 5;
    const int col   = warp * 16 + (lane & 15);
    const int half  = lane >> 4;         // which 64-wide k slice
    const int kbase = half * 64;
    const int row0  = blockIdx.x * 2;

    // ---- load weight slices into registers as packed pairs ----
    u64 wp[32], Wp[32];
    #pragma unroll
    for (int i = 0; i < 32; i++) {
        int k = kbase + 2 * i;
        wp[i] = pk2(w[(size_t)k * H_ + col],  w[(size_t)(k + 1) * H_ + col]);
        Wp[i] = pk2(Wr[(size_t)k * H_ + col], Wr[(size_t)(k + 1) * H_ + col]);
    }
    const float bcol = bias[col];

    // ---- x streaming role: thread owns (xrow, xd) element of each step ----
    const int xrow = tid >> 7;   // 0 or 1
    const int xd   = tid & 127;
    const float* xptr = x + ((size_t)(row0 + xrow) * T_) * D_ + xd;

    // ================= t = 0 : state0 = tanh(x0 @ w + b) =================
    s_x[xrow][xd] = xptr[0];
    __syncthreads();
    {
        const u64x2* xv0 = (const u64x2*)&s_x[0][kbase];
        const u64x2* xv1 = (const u64x2*)&s_x[1][kbase];
        u64 a0 = 0, b0 = 0, a1 = 0, b1 = 0;
        #pragma unroll
        for (int i = 0; i < 16; i++) {
            u64x2 xa = xv0[i];
            u64x2 xb = xv1[i];
            a0 = ffma2(xa.a, wp[2*i],   a0);
            b0 = ffma2(xa.b, wp[2*i+1], b0);
            a1 = ffma2(xb.a, wp[2*i],   a1);
            b1 = ffma2(xb.b, wp[2*i+1], b1);
        }
        float lo, hi, s0, s1;
        upk2(a0, lo, hi); s0  = lo + hi;
        upk2(b0, lo, hi); s0 += lo + hi;
        upk2(a1, lo, hi); s1  = lo + hi;
        upk2(b1, lo, hi); s1 += lo + hi;
        s0 += __shfl_xor_sync(0xffffffffu, s0, 16);
        s1 += __shfl_xor_sync(0xffffffffu, s1, 16);
        float st0 = tanhf(s0 + bcol);
        float st1 = tanhf(s1 + bcol);
        __syncthreads();              // all reads of s_x done before overwrite
        if (half == 0) {
            s_state[0][0][col] = st0;
            s_state[0][1][col] = st1;
        }
        s_x[xrow][xd] = xptr[D_];     // load x[1]
    }
    __syncthreads();

    // ================= t = 1 .. T-1 : y = tanh(xt@w + b + s@Wr) ==========
    int cur = 0;
    for (int t = 1; t < T_; t++) {
        // prefetch next timestep's x element (hidden behind this step's math)
        float xnext = 0.0f;
        if (t + 1 < T_) xnext = xptr[(size_t)(t + 1) * D_];

        const u64x2* xv0 = (const u64x2*)&s_x[0][kbase];
        const u64x2* xv1 = (const u64x2*)&s_x[1][kbase];
        const u64x2* sv0 = (const u64x2*)&s_state[cur][0][kbase];
        const u64x2* sv1 = (const u64x2*)&s_state[cur][1][kbase];

        u64 a0 = 0, b0 = 0, a1 = 0, b1 = 0;
        #pragma unroll
        for (int i = 0; i < 16; i++) {
            u64x2 xa = xv0[i];
            u64x2 xb = xv1[i];
            u64x2 sa = sv0[i];
            u64x2 sb = sv1[i];
            a0 = ffma2(xa.a, wp[2*i],   a0);
            b0 = ffma2(xa.b, wp[2*i+1], b0);
            a1 = ffma2(xb.a, wp[2*i],   a1);
            b1 = ffma2(xb.b, wp[2*i+1], b1);
            a0 = ffma2(sa.a, Wp[2*i],   a0);
            b0 = ffma2(sa.b, Wp[2*i+1], b0);
            a1 = ffma2(sb.a, Wp[2*i],   a1);
            b1 = ffma2(sb.b, Wp[2*i+1], b1);
        }
        float lo, hi, s0, s1;
        upk2(a0, lo, hi); s0  = lo + hi;
        upk2(b0, lo, hi); s0 += lo + hi;
        upk2(a1, lo, hi); s1  = lo + hi;
        upk2(b1, lo, hi); s1 += lo + hi;
        s0 += __shfl_xor_sync(0xffffffffu, s0, 16);
        s1 += __shfl_xor_sync(0xffffffffu, s1, 16);
        float y0 = tanhf(s0 + bcol);
        float y1 = tanhf(s1 + bcol);

        __syncthreads();              // reads of s_x / s_state[cur] complete
        int nxt = cur ^ 1;
        if (half == 0) {
            s_state[nxt][0][col] = y0;
            s_state[nxt][1][col] = y1;
        }
        s_x[xrow][xd] = xnext;
        __syncthreads();              // new state + new x visible
        cur = nxt;
    }

    // ---- write final state ----
    if (half == 0) {
        out[(size_t)row0 * H_ + col]       = s_state[cur][0][col];
        out[(size_t)(row0 + 1) * H_ + col] = s_state[cur][1][col];
    }
}

extern "C" void kernel_launch(void* const* d_in, const int* in_sizes, int n_in,
                              void* d_out, int out_size)
{
    const float* x    = (const float*)d_in[0];  // [256,1024,128]
    const float* w    = (const float*)d_in[1];  // [128,128]
    const float* Wr   = (const float*)d_in[2];  // [128,128]
    const float* bias = (const float*)d_in[3];  // [128]
    float* out = (float*)d_out;                 // [256,128]

    rnn_fused<<<B_ / 2, 256>>>(x, w, Wr, bias, out);
}